// round 1
// baseline (speedup 1.0000x reference)
#include <cuda_runtime.h>

#define NB 16
#define CC 64
#define TT 512
#define VV 25
#define DD 16
#define SS 256
#define NVB (NB*VV)
#define SB 16

// scratch (device globals: allocation-free rule)
__device__ float g_xp[(size_t)NVB*TT*CC];   // [nv][t][d]  52.4 MB
__device__ float g_q [(size_t)NVB*TT*DD];   // [nv][t][j]  13.1 MB
__device__ float g_kk[(size_t)NVB*TT*DD];   // [nv][t][j]  13.1 MB

// ---------------------------------------------------------------------------
// Kernel A: xp[n,v,t,:] = x[n,:,t,v]^T W ; q = xp@alpha ; kk = xp@phi
// one CTA per (n,v), 256 threads = 4 t-rows x 64 d
// ---------------------------------------------------------------------------
__global__ void __launch_bounds__(256) xp_kernel(
    const float* __restrict__ x, const float* __restrict__ W,
    const float* __restrict__ alpha, const float* __restrict__ phi)
{
    __shared__ float sW[CC*CC];
    __shared__ float sA[CC*DD];
    __shared__ float sP[CC*DD];
    __shared__ float xs [4][CC];
    __shared__ float xps[4][CC];

    int nv = blockIdx.x;
    int n = nv / VV, v = nv - n*VV;
    int tid = threadIdx.x;
    int ty = tid >> 6;       // 0..3  (t sub-row)
    int d  = tid & 63;       // 0..63 (output channel / input channel for load)

    for (int i = tid; i < CC*CC; i += 256) sW[i] = W[i];
    for (int i = tid; i < CC*DD; i += 256) { sA[i] = alpha[i]; sP[i] = phi[i]; }
    __syncthreads();

    const float* xb = x + (size_t)n*CC*TT*VV + v;     // x[n, c, t, v]
    float* xpb = g_xp + (size_t)nv*TT*CC;
    float* qb  = g_q  + (size_t)nv*TT*DD;
    float* kb  = g_kk + (size_t)nv*TT*DD;

    for (int t0 = 0; t0 < TT; t0 += 4) {
        int t = t0 + ty;
        xs[ty][d] = xb[(d*TT + t)*VV];          // c = d lane
        __syncthreads();
        float acc = 0.f;
        #pragma unroll
        for (int c = 0; c < CC; c++) acc = fmaf(xs[ty][c], sW[c*CC + d], acc);
        xps[ty][d] = acc;
        xpb[t*CC + d] = acc;
        __syncthreads();
        if (d < 32) {
            const float* M = (d < DD) ? sA : sP;
            int dd = d & 15;
            float a = 0.f;
            #pragma unroll
            for (int c = 0; c < CC; c++) a = fmaf(xps[ty][c], M[c*DD + dd], a);
            if (d < DD) qb[t*DD + dd] = a; else kb[t*DD + dd] = a;
        }
        __syncthreads();
    }
}

// ---------------------------------------------------------------------------
// Kernel B: per (n,v) — attention rows (downsampled) + softmax + band prior,
// then out = att @ xp, written transposed to d_out[n, d, s, v].
// 256 threads/CTA, ~197 KB dynamic smem (1 CTA/SM).
// ---------------------------------------------------------------------------
__global__ void __launch_bounds__(256) attn_kernel(
    const float* __restrict__ karr, float* __restrict__ out)
{
    extern __shared__ float sm[];
    float* s_xp  = sm;                  // [512][64]   131072 B
    float* s_kkT = s_xp  + TT*CC;       // [16][512]    32768 B
    float* s_att = s_kkT + DD*TT;       // [SB][512]    32768 B
    float* s_q   = s_att + SB*TT;       // [SB][16]      1024 B
    float* s_red = s_q   + SB*DD;       // [128][8]      4096 B
    __shared__ float s_k[16];

    int nv = blockIdx.x;
    int n = nv / VV, v = nv - n*VV;
    int tid = threadIdx.x;
    if (tid < 9) s_k[tid] = karr[tid];

    // stage xp tile (vectorized, coalesced)
    const float* xpg = g_xp + (size_t)nv*TT*CC;
    for (int i = tid; i < TT*CC/4; i += 256)
        ((float4*)s_xp)[i] = ((const float4*)xpg)[i];
    // stage kk transposed: s_kkT[j][t]
    const float* kg = g_kk + (size_t)nv*TT*DD;
    for (int i = tid; i < TT*DD; i += 256) {
        int t = i >> 4, j = i & 15;
        s_kkT[j*TT + t] = kg[i];
    }
    __syncthreads();

    const float* qg = g_q + (size_t)nv*TT*DD;

    const int si     = tid >> 4;        // attention row within tile (0..15)
    const int lane16 = tid & 15;
    const int d4     = tid & 15;        // float4 column (16 x 4 = 64 d)
    const int sg     = (tid >> 4) & 7;  // s-group: rows sg and sg+8
    const int tsplit = tid >> 7;        // 0/1 : t-range half

    for (int s0 = 0; s0 < SS; s0 += SB) {
        // load q rows for this tile (row s -> source t = 2s)
        s_q[(tid >> 4)*DD + (tid & 15)] = qg[(2*(s0 + (tid >> 4)))*DD + (tid & 15)];
        __syncthreads();

        // ---- attention scores: row si, t' = i*64 + lane16*4 + c ----
        float qreg[DD];
        #pragma unroll
        for (int j = 0; j < DD; j++) qreg[j] = s_q[si*DD + j] * (1.0f/16.0f);

        float4 av[8];
        #pragma unroll
        for (int i = 0; i < 8; i++) av[i] = make_float4(0.f,0.f,0.f,0.f);
        #pragma unroll
        for (int j = 0; j < DD; j++) {
            const float4* kr = (const float4*)(s_kkT + j*TT);
            float qj = qreg[j];
            #pragma unroll
            for (int i = 0; i < 8; i++) {
                float4 kv = kr[i*16 + lane16];
                av[i].x = fmaf(qj, kv.x, av[i].x);
                av[i].y = fmaf(qj, kv.y, av[i].y);
                av[i].z = fmaf(qj, kv.z, av[i].z);
                av[i].w = fmaf(qj, kv.w, av[i].w);
            }
        }
        // ---- softmax over the row (32 local values + 16-lane shuffle) ----
        float m = -1e30f;
        #pragma unroll
        for (int i = 0; i < 8; i++)
            m = fmaxf(m, fmaxf(fmaxf(av[i].x, av[i].y), fmaxf(av[i].z, av[i].w)));
        #pragma unroll
        for (int o = 8; o > 0; o >>= 1)
            m = fmaxf(m, __shfl_xor_sync(0xffffffffu, m, o));
        float ssum = 0.f;
        #pragma unroll
        for (int i = 0; i < 8; i++) {
            av[i].x = __expf(av[i].x - m); ssum += av[i].x;
            av[i].y = __expf(av[i].y - m); ssum += av[i].y;
            av[i].z = __expf(av[i].z - m); ssum += av[i].z;
            av[i].w = __expf(av[i].w - m); ssum += av[i].w;
        }
        #pragma unroll
        for (int o = 8; o > 0; o >>= 1)
            ssum += __shfl_xor_sync(0xffffffffu, ssum, o);
        float inv = 1.0f / ssum;

        int tRow = 2*(s0 + si);
        float4* arow = (float4*)(s_att + si*TT);
        #pragma unroll
        for (int i = 0; i < 8; i++) {
            int tb = i*64 + lane16*4;
            float4 r;
            r.x = av[i].x * inv; r.y = av[i].y * inv;
            r.z = av[i].z * inv; r.w = av[i].w * inv;
            int o0 = tb + 0 - tRow + 4; if ((unsigned)o0 < 9u) r.x += s_k[o0];
            int o1 = tb + 1 - tRow + 4; if ((unsigned)o1 < 9u) r.y += s_k[o1];
            int o2 = tb + 2 - tRow + 4; if ((unsigned)o2 < 9u) r.z += s_k[o2];
            int o3 = tb + 3 - tRow + 4; if ((unsigned)o3 < 9u) r.w += s_k[o3];
            arow[i*16 + lane16] = r;
        }
        __syncthreads();

        // ---- out tile: [16 s][64 d] = att[16][512] @ xp[512][64] ----
        const float4* xp4 = (const float4*)s_xp;
        const float* attA = s_att + sg*TT;
        const float* attB = s_att + (sg+8)*TT;
        float4 acc0 = make_float4(0.f,0.f,0.f,0.f);
        float4 acc1 = make_float4(0.f,0.f,0.f,0.f);
        int tbase = tsplit * 256;
        #pragma unroll 4
        for (int t = tbase; t < tbase + 256; t++) {
            float4 xv = xp4[t*16 + d4];
            float a0 = attA[t], a1 = attB[t];
            acc0.x = fmaf(a0, xv.x, acc0.x);
            acc0.y = fmaf(a0, xv.y, acc0.y);
            acc0.z = fmaf(a0, xv.z, acc0.z);
            acc0.w = fmaf(a0, xv.w, acc0.w);
            acc1.x = fmaf(a1, xv.x, acc1.x);
            acc1.y = fmaf(a1, xv.y, acc1.y);
            acc1.z = fmaf(a1, xv.z, acc1.z);
            acc1.w = fmaf(a1, xv.w, acc1.w);
        }
        if (tsplit == 1) {
            float4* red4 = (float4*)s_red;
            red4[(sg*16 + d4)*2 + 0] = acc0;
            red4[(sg*16 + d4)*2 + 1] = acc1;
        }
        __syncthreads();
        if (tsplit == 0) {
            float4* red4 = (float4*)s_red;
            float4 p0 = red4[(sg*16 + d4)*2 + 0];
            float4 p1 = red4[(sg*16 + d4)*2 + 1];
            acc0.x += p0.x; acc0.y += p0.y; acc0.z += p0.z; acc0.w += p0.w;
            acc1.x += p1.x; acc1.y += p1.y; acc1.z += p1.z; acc1.w += p1.w;
            int sA = s0 + sg, sBr = s0 + sg + 8;
            int dbase = d4 * 4;
            float r0[4] = {acc0.x, acc0.y, acc0.z, acc0.w};
            float r1[4] = {acc1.x, acc1.y, acc1.z, acc1.w};
            #pragma unroll
            for (int c = 0; c < 4; c++) {
                out[(((size_t)n*CC + dbase + c)*SS + sA )*VV + v] = r0[c];
                out[(((size_t)n*CC + dbase + c)*SS + sBr)*VV + v] = r1[c];
            }
        }
    }
}

extern "C" void kernel_launch(void* const* d_in, const int* in_sizes, int n_in,
                              void* d_out, int out_size)
{
    const float* x     = (const float*)d_in[0];
    const float* W     = (const float*)d_in[1];
    const float* alpha = (const float*)d_in[2];
    const float* phi   = (const float*)d_in[3];
    const float* karr  = (const float*)d_in[4];
    float* out = (float*)d_out;

    const int smemB = (TT*CC + DD*TT + SB*TT + SB*DD + 128*8) * sizeof(float); // 201728 B
    cudaFuncSetAttribute(attn_kernel, cudaFuncAttributeMaxDynamicSharedMemorySize, smemB);

    xp_kernel<<<NVB, 256>>>(x, W, alpha, phi);
    attn_kernel<<<NVB, 256, smemB>>>(karr, out);
}

// round 2
// speedup vs baseline: 1.2302x; 1.2302x over previous
#include <cuda_runtime.h>

#define CC 64
#define TT 512
#define VV 25
#define DD 16
#define SS 256
#define NVB 400

// shared-memory float offsets
#define XP_STR   68
#define KKT_STR  516
#define OFF_KKT  (512*XP_STR)            // 34816
#define OFF_QA   (OFF_KKT + 16*KKT_STR)  // 43072
#define OFF_A    (OFF_QA + 256*16)       // 47168  (overlay region, 8256 floats)
#define A_SIZE   8256
#define OFF_KB   (OFF_A + A_SIZE)        // 55424
#define OFF_RED  (OFF_KB + 16)           // 55440
#define SMEM_FLOATS (OFF_RED + 64)       // 55504 -> 222016 bytes

__global__ void __launch_bounds__(256, 1) fused_tgat_kernel(
    const float* __restrict__ x, const float* __restrict__ W,
    const float* __restrict__ alpha, const float* __restrict__ phi,
    const float* __restrict__ karr, float* __restrict__ out)
{
    extern __shared__ float sm[];
    float* s_xp  = sm;                 // [512][68]
    float* s_kkT = sm + OFF_KKT;       // [16][516]
    float* s_qa  = sm + OFF_QA;        // [256][16]
    float* s_A   = sm + OFF_A;         // overlay region
    float* s_kb  = sm + OFF_KB;        // band kernel (16, zero padded)
    float* s_red = sm + OFF_RED;       // softmax cross-warp exchange

    const int tid = threadIdx.x;
    const int nv  = blockIdx.x;
    const int n   = nv / VV, v = nv - n * VV;

    // ---------------- phase 0: stage W + band kernel ----------------
    float* xs = s_A;            // [64][65]  (4160 floats)
    float* sW = s_A + 4160;     // [64][64]  (4096 floats)
    for (int i = tid; i < 64 * 64; i += 256) sW[i] = W[i];
    if (tid < 16) s_kb[tid] = (tid < 9) ? karr[tid] : 0.0f;
    __syncthreads();

    // ---------------- phase 1: xp = x^T W  (8 chunks of 64 t) ----------------
    const float* xb = x + ((size_t)n * CC * TT) * VV + v;
    float xreg[16];
    #pragma unroll
    for (int kx = 0; kx < 16; kx++) {
        int idx = tid + kx * 256; int c = idx >> 6, t = idx & 63;
        xreg[kx] = __ldg(xb + ((size_t)c * TT + t) * VV);
    }
    const int tg = tid >> 3, dg = tid & 7;
    for (int ch = 0; ch < 8; ch++) {
        #pragma unroll
        for (int kx = 0; kx < 16; kx++) {
            int idx = tid + kx * 256; int c = idx >> 6, t = idx & 63;
            xs[c * 65 + t] = xreg[kx];
        }
        __syncthreads();
        if (ch < 7) {
            int t0n = (ch + 1) * 64;
            #pragma unroll
            for (int kx = 0; kx < 16; kx++) {
                int idx = tid + kx * 256; int c = idx >> 6, t = idx & 63;
                xreg[kx] = __ldg(xb + ((size_t)c * TT + t0n + t) * VV);
            }
        }
        float acc0[8], acc1[8];
        #pragma unroll
        for (int i = 0; i < 8; i++) { acc0[i] = 0.f; acc1[i] = 0.f; }
        #pragma unroll 8
        for (int c = 0; c < 64; c++) {
            float x0 = xs[c * 65 + tg * 2];
            float x1 = xs[c * 65 + tg * 2 + 1];
            float4 w0 = *(const float4*)(sW + c * 64 + dg * 8);
            float4 w1 = *(const float4*)(sW + c * 64 + dg * 8 + 4);
            acc0[0] = fmaf(x0, w0.x, acc0[0]); acc1[0] = fmaf(x1, w0.x, acc1[0]);
            acc0[1] = fmaf(x0, w0.y, acc0[1]); acc1[1] = fmaf(x1, w0.y, acc1[1]);
            acc0[2] = fmaf(x0, w0.z, acc0[2]); acc1[2] = fmaf(x1, w0.z, acc1[2]);
            acc0[3] = fmaf(x0, w0.w, acc0[3]); acc1[3] = fmaf(x1, w0.w, acc1[3]);
            acc0[4] = fmaf(x0, w1.x, acc0[4]); acc1[4] = fmaf(x1, w1.x, acc1[4]);
            acc0[5] = fmaf(x0, w1.y, acc0[5]); acc1[5] = fmaf(x1, w1.y, acc1[5]);
            acc0[6] = fmaf(x0, w1.z, acc0[6]); acc1[6] = fmaf(x1, w1.z, acc1[6]);
            acc0[7] = fmaf(x0, w1.w, acc0[7]); acc1[7] = fmaf(x1, w1.w, acc1[7]);
        }
        float* r0 = s_xp + (size_t)(ch * 64 + tg * 2) * XP_STR + dg * 8;
        #pragma unroll
        for (int i = 0; i < 8; i++) { r0[i] = acc0[i]; r0[XP_STR + i] = acc1[i]; }
        __syncthreads();
    }

    // ---------------- phase 2: kkT = (xp @ phi)^T ; q = (xp @ alpha)/16 at even t ----------------
    float* sAl = s_A;            // [64][16]  alpha pre-scaled by 1/16
    float* sPh = s_A + 1024;     // [64][16]
    for (int i = tid; i < 1024; i += 256) {
        sAl[i] = alpha[i] * 0.0625f;
        sPh[i] = phi[i];
    }
    __syncthreads();
    {
        const int t0 = tid * 2;
        float k0[16], k1[16], qa[16];
        #pragma unroll
        for (int j = 0; j < 16; j++) { k0[j] = 0.f; k1[j] = 0.f; qa[j] = 0.f; }
        const float* xr = s_xp + (size_t)t0 * XP_STR;
        #pragma unroll 4
        for (int c = 0; c < 64; c++) {
            float x0 = xr[c];
            float x1 = xr[XP_STR + c];
            const float4* ph4 = (const float4*)(sPh + c * 16);
            const float4* al4 = (const float4*)(sAl + c * 16);
            #pragma unroll
            for (int jq = 0; jq < 4; jq++) {
                float4 pv = ph4[jq];
                float4 av = al4[jq];
                k0[jq*4+0] = fmaf(x0, pv.x, k0[jq*4+0]); k1[jq*4+0] = fmaf(x1, pv.x, k1[jq*4+0]);
                k0[jq*4+1] = fmaf(x0, pv.y, k0[jq*4+1]); k1[jq*4+1] = fmaf(x1, pv.y, k1[jq*4+1]);
                k0[jq*4+2] = fmaf(x0, pv.z, k0[jq*4+2]); k1[jq*4+2] = fmaf(x1, pv.z, k1[jq*4+2]);
                k0[jq*4+3] = fmaf(x0, pv.w, k0[jq*4+3]); k1[jq*4+3] = fmaf(x1, pv.w, k1[jq*4+3]);
                qa[jq*4+0] = fmaf(x0, av.x, qa[jq*4+0]);
                qa[jq*4+1] = fmaf(x0, av.y, qa[jq*4+1]);
                qa[jq*4+2] = fmaf(x0, av.z, qa[jq*4+2]);
                qa[jq*4+3] = fmaf(x0, av.w, qa[jq*4+3]);
            }
        }
        #pragma unroll
        for (int j = 0; j < 16; j++) {
            s_kkT[j * KKT_STR + t0]     = k0[j];
            s_kkT[j * KKT_STR + t0 + 1] = k1[j];
            s_qa[tid * 16 + j] = qa[j];       // q row for s = tid (t = 2s)
        }
    }
    __syncthreads();

    // ---------------- phase 3: 16 tiles of 16 attention rows ----------------
    const int r4   = tid >> 6;        // row group (4 rows each)
    const int tl   = tid & 63;        // t lane: covers t in [tl*8, tl*8+8)
    const int wpid = tid >> 5;
    const int lane = tid & 31;
    // out-phase mapping
    const int sblk  = tid >> 7;           // 0..1 (8 rows each)
    const int dgrp  = (tid >> 3) & 15;    // 0..15 (4 d each)
    const int chunk = tid & 7;            // 0..7  (t-f4 interleave)

    const float4* kk4 = (const float4*)s_kkT;   // row stride 129 f4
    const float4* xp4 = (const float4*)s_xp;    // row stride 17 f4
    float*  s_att = s_A;                         // [16][516]
    float4* s_p4  = (float4*)s_A;                // [256][8] f4 partials (after att is dead)

    for (int tile = 0; tile < 16; tile++) {
        const int s0 = tile * 16;

        // ---- scores: rows r4*4..+3, t = tl*8..+7 ----
        float4 acA[4], acB[4];
        #pragma unroll
        for (int r = 0; r < 4; r++) {
            acA[r] = make_float4(0.f,0.f,0.f,0.f);
            acB[r] = make_float4(0.f,0.f,0.f,0.f);
        }
        #pragma unroll
        for (int j = 0; j < 16; j++) {
            float4 kA = kk4[j * 129 + tl * 2];
            float4 kB = kk4[j * 129 + tl * 2 + 1];
            #pragma unroll
            for (int r = 0; r < 4; r++) {
                float qv = s_qa[(s0 + r4 * 4 + r) * 16 + j];
                acA[r].x = fmaf(qv, kA.x, acA[r].x);
                acA[r].y = fmaf(qv, kA.y, acA[r].y);
                acA[r].z = fmaf(qv, kA.z, acA[r].z);
                acA[r].w = fmaf(qv, kA.w, acA[r].w);
                acB[r].x = fmaf(qv, kB.x, acB[r].x);
                acB[r].y = fmaf(qv, kB.y, acB[r].y);
                acB[r].z = fmaf(qv, kB.z, acB[r].z);
                acB[r].w = fmaf(qv, kB.w, acB[r].w);
            }
        }
        // ---- softmax over t (64 lanes = 2 warps per row group) ----
        float mrow[4];
        #pragma unroll
        for (int r = 0; r < 4; r++) {
            float m = fmaxf(fmaxf(fmaxf(acA[r].x, acA[r].y), fmaxf(acA[r].z, acA[r].w)),
                            fmaxf(fmaxf(acB[r].x, acB[r].y), fmaxf(acB[r].z, acB[r].w)));
            #pragma unroll
            for (int off = 16; off > 0; off >>= 1)
                m = fmaxf(m, __shfl_xor_sync(0xffffffffu, m, off));
            mrow[r] = m;
        }
        if (lane == 0) {
            #pragma unroll
            for (int r = 0; r < 4; r++) s_red[wpid * 4 + r] = mrow[r];
        }
        __syncthreads();
        #pragma unroll
        for (int r = 0; r < 4; r++)
            mrow[r] = fmaxf(s_red[(r4 * 2) * 4 + r], s_red[(r4 * 2 + 1) * 4 + r]);

        float srow[4];
        #pragma unroll
        for (int r = 0; r < 4; r++) {
            float m = mrow[r];
            acA[r].x = __expf(acA[r].x - m); acA[r].y = __expf(acA[r].y - m);
            acA[r].z = __expf(acA[r].z - m); acA[r].w = __expf(acA[r].w - m);
            acB[r].x = __expf(acB[r].x - m); acB[r].y = __expf(acB[r].y - m);
            acB[r].z = __expf(acB[r].z - m); acB[r].w = __expf(acB[r].w - m);
            float s = acA[r].x + acA[r].y + acA[r].z + acA[r].w
                    + acB[r].x + acB[r].y + acB[r].z + acB[r].w;
            #pragma unroll
            for (int off = 16; off > 0; off >>= 1)
                s += __shfl_xor_sync(0xffffffffu, s, off);
            srow[r] = s;
        }
        if (lane == 0) {
            #pragma unroll
            for (int r = 0; r < 4; r++) s_red[32 + wpid * 4 + r] = srow[r];
        }
        __syncthreads();

        // ---- write normalized att + band prior ----
        #pragma unroll
        for (int r = 0; r < 4; r++) {
            float tot = s_red[32 + (r4 * 2) * 4 + r] + s_red[32 + (r4 * 2 + 1) * 4 + r];
            float inv = 1.0f / tot;
            int row = r4 * 4 + r;
            int tRow = 2 * (s0 + row);
            int tb = tl * 8;
            float4 e0, e1;
            e0.x = acA[r].x * inv; e0.y = acA[r].y * inv;
            e0.z = acA[r].z * inv; e0.w = acA[r].w * inv;
            e1.x = acB[r].x * inv; e1.y = acB[r].y * inv;
            e1.z = acB[r].z * inv; e1.w = acB[r].w * inv;
            int o;
            o = tb + 0 - tRow + 4; if ((unsigned)o < 9u) e0.x += s_kb[o];
            o = tb + 1 - tRow + 4; if ((unsigned)o < 9u) e0.y += s_kb[o];
            o = tb + 2 - tRow + 4; if ((unsigned)o < 9u) e0.z += s_kb[o];
            o = tb + 3 - tRow + 4; if ((unsigned)o < 9u) e0.w += s_kb[o];
            o = tb + 4 - tRow + 4; if ((unsigned)o < 9u) e1.x += s_kb[o];
            o = tb + 5 - tRow + 4; if ((unsigned)o < 9u) e1.y += s_kb[o];
            o = tb + 6 - tRow + 4; if ((unsigned)o < 9u) e1.z += s_kb[o];
            o = tb + 7 - tRow + 4; if ((unsigned)o < 9u) e1.w += s_kb[o];
            float4* arow = (float4*)(s_att + row * KKT_STR);
            arow[tl * 2]     = e0;
            arow[tl * 2 + 1] = e1;
        }
        __syncthreads();

        // ---- out tile: [16 s][64 d] = att[16][512] @ xp[512][64], 8-way t split ----
        float4 oac[8];
        #pragma unroll
        for (int r = 0; r < 8; r++) oac[r] = make_float4(0.f,0.f,0.f,0.f);
        #pragma unroll 4
        for (int it = 0; it < 16; it++) {
            int f4i = it * 8 + chunk;             // t-f4 index 0..127
            float4 xv0 = xp4[(f4i * 4 + 0) * 17 + dgrp];
            float4 xv1 = xp4[(f4i * 4 + 1) * 17 + dgrp];
            float4 xv2 = xp4[(f4i * 4 + 2) * 17 + dgrp];
            float4 xv3 = xp4[(f4i * 4 + 3) * 17 + dgrp];
            #pragma unroll
            for (int r = 0; r < 8; r++) {
                float4 av = ((const float4*)(s_att + (sblk * 8 + r) * KKT_STR))[f4i];
                oac[r].x = fmaf(av.x, xv0.x, oac[r].x);
                oac[r].y = fmaf(av.x, xv0.y, oac[r].y);
                oac[r].z = fmaf(av.x, xv0.z, oac[r].z);
                oac[r].w = fmaf(av.x, xv0.w, oac[r].w);
                oac[r].x = fmaf(av.y, xv1.x, oac[r].x);
                oac[r].y = fmaf(av.y, xv1.y, oac[r].y);
                oac[r].z = fmaf(av.y, xv1.z, oac[r].z);
                oac[r].w = fmaf(av.y, xv1.w, oac[r].w);
                oac[r].x = fmaf(av.z, xv2.x, oac[r].x);
                oac[r].y = fmaf(av.z, xv2.y, oac[r].y);
                oac[r].z = fmaf(av.z, xv2.z, oac[r].z);
                oac[r].w = fmaf(av.z, xv2.w, oac[r].w);
                oac[r].x = fmaf(av.w, xv3.x, oac[r].x);
                oac[r].y = fmaf(av.w, xv3.y, oac[r].y);
                oac[r].z = fmaf(av.w, xv3.z, oac[r].z);
                oac[r].w = fmaf(av.w, xv3.w, oac[r].w);
            }
        }
        __syncthreads();   // att reads done; region becomes partial buffer

        #pragma unroll
        for (int r = 0; r < 8; r++) {
            int o4 = (sblk * 8 + r) * 16 + dgrp;   // output f4 id 0..255
            s_p4[o4 * 8 + chunk] = oac[r];
        }
        __syncthreads();

        // ---- reduce 8 partials + store to gmem: out[n][d][s][v] ----
        {
            const float4* pr = s_p4 + tid * 8;
            float4 a0 = pr[0], a1 = pr[1], a2 = pr[2], a3 = pr[3];
            float4 a4 = pr[4], a5 = pr[5], a6 = pr[6], a7 = pr[7];
            float4 sum;
            sum.x = ((a0.x + a1.x) + (a2.x + a3.x)) + ((a4.x + a5.x) + (a6.x + a7.x));
            sum.y = ((a0.y + a1.y) + (a2.y + a3.y)) + ((a4.y + a5.y) + (a6.y + a7.y));
            sum.z = ((a0.z + a1.z) + (a2.z + a3.z)) + ((a4.z + a5.z) + (a6.z + a7.z));
            sum.w = ((a0.w + a1.w) + (a2.w + a3.w)) + ((a4.w + a5.w) + (a6.w + a7.w));
            int row = tid >> 4, dq = tid & 15;
            int s = s0 + row;
            size_t ob = (((size_t)n * CC + dq * 4) * SS + s) * VV + v;
            const size_t dstride = (size_t)SS * VV;
            out[ob]               = sum.x;
            out[ob + dstride]     = sum.y;
            out[ob + 2 * dstride] = sum.z;
            out[ob + 3 * dstride] = sum.w;
        }
        __syncthreads();
    }
}

extern "C" void kernel_launch(void* const* d_in, const int* in_sizes, int n_in,
                              void* d_out, int out_size)
{
    const float* x     = (const float*)d_in[0];
    const float* W     = (const float*)d_in[1];
    const float* alpha = (const float*)d_in[2];
    const float* phi   = (const float*)d_in[3];
    const float* karr  = (const float*)d_in[4];
    float* out = (float*)d_out;

    const int smemB = SMEM_FLOATS * sizeof(float);   // 222016 bytes
    cudaFuncSetAttribute(fused_tgat_kernel,
                         cudaFuncAttributeMaxDynamicSharedMemorySize, smemB);
    fused_tgat_kernel<<<NVB, 256, smemB>>>(x, W, alpha, phi, karr, out);
}

// round 3
// speedup vs baseline: 1.9529x; 1.5874x over previous
#include <cuda_runtime.h>

#define CC 64
#define TT 512
#define VV 25
#define DD 16
#define SS 256
#define NVB 400

#define XP_STR   68
#define KKT_STR  516
#define OFF_KKT  34816
#define OFF_QA   43072
#define OFF_A    47168
#define OFF_KB   55488
#define OFF_RED  55504
#define SMEM_FLOATS 55568      // 222272 bytes

typedef unsigned long long u64;

__device__ __forceinline__ u64 pk2(float a, float b) {
    u64 r; asm("mov.b64 %0, {%1,%2};" : "=l"(r) : "f"(a), "f"(b)); return r;
}
__device__ __forceinline__ u64 f2(u64 a, u64 b, u64 c) {
    u64 d; asm("fma.rn.f32x2 %0, %1, %2, %3;" : "=l"(d) : "l"(a), "l"(b), "l"(c)); return d;
}
__device__ __forceinline__ u64 ad2(u64 a, u64 b) {
    u64 d; asm("add.rn.f32x2 %0, %1, %2;" : "=l"(d) : "l"(a), "l"(b)); return d;
}
__device__ __forceinline__ float2 up2(u64 a) {
    float lo, hi; asm("mov.b64 {%0,%1}, %2;" : "=f"(lo), "=f"(hi) : "l"(a));
    return make_float2(lo, hi);
}

__global__ void __launch_bounds__(512, 1) tgat3_kernel(
    const float* __restrict__ x, const float* __restrict__ W,
    const float* __restrict__ alpha, const float* __restrict__ phi,
    const float* __restrict__ karr, float* __restrict__ out)
{
    extern __shared__ float sm[];
    float* s_xp  = sm;                 // [512][68]
    float* s_kkT = sm + OFF_KKT;       // [16][516]
    float* s_qa  = sm + OFF_QA;        // [256][16]   (= sW during phase 1)
    float* s_A   = sm + OFF_A;         // 8320-float overlay
    float* s_kb  = sm + OFF_KB;
    float* s_red = sm + OFF_RED;

    const int tid = threadIdx.x;
    const int nv = blockIdx.x;
    const int n = nv / VV, v = nv - n * VV;

    // ---------- phase 0: W -> smem (in qa region), band kernel ----------
    float* sW = s_qa;
    for (int i = tid; i < CC * CC; i += 512) sW[i] = W[i];
    if (tid < 16) s_kb[tid] = (tid < 9) ? karr[tid] : 0.0f;

    // ---------- phase 1: xp = x^T W, 4 chunks of 128 t ----------
    const float* xb = x + ((size_t)n * CC * TT) * VV + v;
    float* xs = s_A;                   // [64][130]
    float xr[16];
    #pragma unroll
    for (int kx = 0; kx < 16; kx++) {
        int idx = tid + kx * 512; int c = idx >> 7, t = idx & 127;
        xr[kx] = __ldg(xb + ((size_t)c * TT + t) * VV);
    }
    const int tg = tid >> 4, dg = tid & 15;
    for (int ch = 0; ch < 4; ch++) {
        if (ch > 0) __syncthreads();                 // xs reads of prev chunk done
        #pragma unroll
        for (int kx = 0; kx < 16; kx++) {
            int idx = tid + kx * 512; int c = idx >> 7, t = idx & 127;
            xs[c * 130 + t] = xr[kx];
        }
        __syncthreads();                             // xs (and sW on ch0) ready
        if (ch < 3) {
            int tb = (ch + 1) * 128;
            #pragma unroll
            for (int kx = 0; kx < 16; kx++) {
                int idx = tid + kx * 512; int c = idx >> 7, t = idx & 127;
                xr[kx] = __ldg(xb + ((size_t)c * TT + tb + t) * VV);
            }
        }
        u64 acc[4][2];
        #pragma unroll
        for (int i = 0; i < 4; i++) { acc[i][0] = pk2(0.f, 0.f); acc[i][1] = acc[i][0]; }
        #pragma unroll 8
        for (int c = 0; c < 64; c++) {
            const float* xrow = xs + c * 130 + tg * 4;
            ulonglong2 wv = *(const ulonglong2*)(sW + c * 64 + dg * 4);
            #pragma unroll
            for (int i = 0; i < 4; i++) {
                u64 xd = pk2(xrow[i], xrow[i]);
                acc[i][0] = f2(xd, wv.x, acc[i][0]);
                acc[i][1] = f2(xd, wv.y, acc[i][1]);
            }
        }
        #pragma unroll
        for (int i = 0; i < 4; i++) {
            ulonglong2 st; st.x = acc[i][0]; st.y = acc[i][1];
            *(ulonglong2*)(s_xp + (size_t)(ch * 128 + tg * 4 + i) * XP_STR + dg * 4) = st;
        }
    }
    __syncthreads();

    // ---------- phase 2: kkT = (xp@phi)^T ; q = (xp@alpha)/16 ----------
    float* sAl = s_A;                  // [64][16]
    float* sPh = s_A + 1024;           // [64][16]
    for (int i = tid; i < 1024; i += 512) { sAl[i] = alpha[i] * 0.0625f; sPh[i] = phi[i]; }
    __syncthreads();
    {
        const int w = tid >> 5, l = tid & 31;
        const int t2 = (w & 7) * 64 + l * 2 + (w >> 3);   // warps 0-7: even t, 8-15: odd
        const bool doq = (w < 8);
        u64 kacc[8], qacc[8];
        #pragma unroll
        for (int j = 0; j < 8; j++) { kacc[j] = pk2(0.f, 0.f); qacc[j] = kacc[j]; }
        #pragma unroll 4
        for (int c4 = 0; c4 < 16; c4++) {
            float4 xv = *(const float4*)(s_xp + (size_t)t2 * XP_STR + c4 * 4);
            float xe[4] = {xv.x, xv.y, xv.z, xv.w};
            #pragma unroll
            for (int e = 0; e < 4; e++) {
                int c = c4 * 4 + e;
                u64 xd = pk2(xe[e], xe[e]);
                const ulonglong2* pp = (const ulonglong2*)(sPh + c * 16);
                ulonglong2 p0 = pp[0], p1 = pp[1], p2 = pp[2], p3 = pp[3];
                kacc[0] = f2(xd, p0.x, kacc[0]); kacc[1] = f2(xd, p0.y, kacc[1]);
                kacc[2] = f2(xd, p1.x, kacc[2]); kacc[3] = f2(xd, p1.y, kacc[3]);
                kacc[4] = f2(xd, p2.x, kacc[4]); kacc[5] = f2(xd, p2.y, kacc[5]);
                kacc[6] = f2(xd, p3.x, kacc[6]); kacc[7] = f2(xd, p3.y, kacc[7]);
                if (doq) {
                    const ulonglong2* aa = (const ulonglong2*)(sAl + c * 16);
                    ulonglong2 a0 = aa[0], a1 = aa[1], a2 = aa[2], a3 = aa[3];
                    qacc[0] = f2(xd, a0.x, qacc[0]); qacc[1] = f2(xd, a0.y, qacc[1]);
                    qacc[2] = f2(xd, a1.x, qacc[2]); qacc[3] = f2(xd, a1.y, qacc[3]);
                    qacc[4] = f2(xd, a2.x, qacc[4]); qacc[5] = f2(xd, a2.y, qacc[5]);
                    qacc[6] = f2(xd, a3.x, qacc[6]); qacc[7] = f2(xd, a3.y, qacc[7]);
                }
            }
        }
        #pragma unroll
        for (int j = 0; j < 8; j++) {
            float2 kv = up2(kacc[j]);
            s_kkT[(2 * j) * KKT_STR + t2]     = kv.x;
            s_kkT[(2 * j + 1) * KKT_STR + t2] = kv.y;
        }
        if (doq) {
            int s = t2 >> 1;
            u64* qrow = (u64*)(s_qa + s * 16);
            #pragma unroll
            for (int j = 0; j < 8; j++) qrow[j] = qacc[j];
        }
    }
    __syncthreads();

    // ---------- phase 3: 16 tiles of 16 s-rows ----------
    const int w = tid >> 5, l = tid & 31;
    const int h = w >> 3, p = w & 7;                 // scores mapping
    const int dgrp = tid & 15, chunk = (tid >> 4) & 15, sblk = tid >> 8;  // out mapping
    float* s_att = s_A;                              // [16][516]
    float* s_p4  = s_A;                              // partials (after att dead)

    for (int tile = 0; tile < 16; tile++) {
        const int s0 = tile * 16;
        const int r0 = 2 * p, r1 = 2 * p + 1;

        // ---- scores: rows r0,r1 ; t-half h ; lane covers f4 (h*64+l) and +32 ----
        u64 aA0[2], aA1[2], aB0[2], aB1[2];
        aA0[0]=aA0[1]=aA1[0]=aA1[1]=aB0[0]=aB0[1]=aB1[0]=aB1[1]=pk2(0.f,0.f);
        const float* kbase = s_kkT + (h * 64 + l) * 4;
        #pragma unroll
        for (int j = 0; j < 16; j++) {
            float q0 = s_qa[(s0 + r0) * 16 + j];
            float q1 = s_qa[(s0 + r1) * 16 + j];
            u64 qd0 = pk2(q0, q0), qd1 = pk2(q1, q1);
            ulonglong2 kA = *(const ulonglong2*)(kbase + j * KKT_STR);
            ulonglong2 kB = *(const ulonglong2*)(kbase + j * KKT_STR + 128);
            aA0[0] = f2(qd0, kA.x, aA0[0]); aA0[1] = f2(qd0, kA.y, aA0[1]);
            aA1[0] = f2(qd1, kA.x, aA1[0]); aA1[1] = f2(qd1, kA.y, aA1[1]);
            aB0[0] = f2(qd0, kB.x, aB0[0]); aB0[1] = f2(qd0, kB.y, aB0[1]);
            aB1[0] = f2(qd1, kB.x, aB1[0]); aB1[1] = f2(qd1, kB.y, aB1[1]);
        }
        float2 A0a = up2(aA0[0]), A0b = up2(aA0[1]);
        float2 B0a = up2(aB0[0]), B0b = up2(aB0[1]);
        float2 A1a = up2(aA1[0]), A1b = up2(aA1[1]);
        float2 B1a = up2(aB1[0]), B1b = up2(aB1[1]);

        float m0 = fmaxf(fmaxf(fmaxf(A0a.x, A0a.y), fmaxf(A0b.x, A0b.y)),
                         fmaxf(fmaxf(B0a.x, B0a.y), fmaxf(B0b.x, B0b.y)));
        float m1 = fmaxf(fmaxf(fmaxf(A1a.x, A1a.y), fmaxf(A1b.x, A1b.y)),
                         fmaxf(fmaxf(B1a.x, B1a.y), fmaxf(B1b.x, B1b.y)));
        #pragma unroll
        for (int o = 16; o > 0; o >>= 1) {
            m0 = fmaxf(m0, __shfl_xor_sync(0xffffffffu, m0, o));
            m1 = fmaxf(m1, __shfl_xor_sync(0xffffffffu, m1, o));
        }
        if (l == 0) { s_red[r0 * 2 + h] = m0; s_red[r1 * 2 + h] = m1; }
        __syncthreads();
        m0 = fmaxf(s_red[r0 * 2], s_red[r0 * 2 + 1]);
        m1 = fmaxf(s_red[r1 * 2], s_red[r1 * 2 + 1]);

        A0a.x = __expf(A0a.x - m0); A0a.y = __expf(A0a.y - m0);
        A0b.x = __expf(A0b.x - m0); A0b.y = __expf(A0b.y - m0);
        B0a.x = __expf(B0a.x - m0); B0a.y = __expf(B0a.y - m0);
        B0b.x = __expf(B0b.x - m0); B0b.y = __expf(B0b.y - m0);
        A1a.x = __expf(A1a.x - m1); A1a.y = __expf(A1a.y - m1);
        A1b.x = __expf(A1b.x - m1); A1b.y = __expf(A1b.y - m1);
        B1a.x = __expf(B1a.x - m1); B1a.y = __expf(B1a.y - m1);
        B1b.x = __expf(B1b.x - m1); B1b.y = __expf(B1b.y - m1);
        float sm0 = (A0a.x + A0a.y) + (A0b.x + A0b.y) + (B0a.x + B0a.y) + (B0b.x + B0b.y);
        float sm1 = (A1a.x + A1a.y) + (A1b.x + A1b.y) + (B1a.x + B1a.y) + (B1b.x + B1b.y);
        #pragma unroll
        for (int o = 16; o > 0; o >>= 1) {
            sm0 += __shfl_xor_sync(0xffffffffu, sm0, o);
            sm1 += __shfl_xor_sync(0xffffffffu, sm1, o);
        }
        if (l == 0) { s_red[32 + r0 * 2 + h] = sm0; s_red[32 + r1 * 2 + h] = sm1; }
        __syncthreads();
        float inv0 = 1.0f / (s_red[32 + r0 * 2] + s_red[32 + r0 * 2 + 1]);
        float inv1 = 1.0f / (s_red[32 + r1 * 2] + s_red[32 + r1 * 2 + 1]);

        // ---- att write + band prior ----
        {
            int tA = h * 256 + l * 4;
            int tB = tA + 128;
            int tr0 = 2 * (s0 + r0), tr1 = 2 * (s0 + r1);
            float4 e; int o;
            e.x = A0a.x * inv0; e.y = A0a.y * inv0; e.z = A0b.x * inv0; e.w = A0b.y * inv0;
            o = tA + 0 - tr0 + 4; if ((unsigned)o < 9u) e.x += s_kb[o];
            o = tA + 1 - tr0 + 4; if ((unsigned)o < 9u) e.y += s_kb[o];
            o = tA + 2 - tr0 + 4; if ((unsigned)o < 9u) e.z += s_kb[o];
            o = tA + 3 - tr0 + 4; if ((unsigned)o < 9u) e.w += s_kb[o];
            *(float4*)(s_att + r0 * KKT_STR + tA) = e;
            e.x = B0a.x * inv0; e.y = B0a.y * inv0; e.z = B0b.x * inv0; e.w = B0b.y * inv0;
            o = tB + 0 - tr0 + 4; if ((unsigned)o < 9u) e.x += s_kb[o];
            o = tB + 1 - tr0 + 4; if ((unsigned)o < 9u) e.y += s_kb[o];
            o = tB + 2 - tr0 + 4; if ((unsigned)o < 9u) e.z += s_kb[o];
            o = tB + 3 - tr0 + 4; if ((unsigned)o < 9u) e.w += s_kb[o];
            *(float4*)(s_att + r0 * KKT_STR + tB) = e;
            e.x = A1a.x * inv1; e.y = A1a.y * inv1; e.z = A1b.x * inv1; e.w = A1b.y * inv1;
            o = tA + 0 - tr1 + 4; if ((unsigned)o < 9u) e.x += s_kb[o];
            o = tA + 1 - tr1 + 4; if ((unsigned)o < 9u) e.y += s_kb[o];
            o = tA + 2 - tr1 + 4; if ((unsigned)o < 9u) e.z += s_kb[o];
            o = tA + 3 - tr1 + 4; if ((unsigned)o < 9u) e.w += s_kb[o];
            *(float4*)(s_att + r1 * KKT_STR + tA) = e;
            e.x = B1a.x * inv1; e.y = B1a.y * inv1; e.z = B1b.x * inv1; e.w = B1b.y * inv1;
            o = tB + 0 - tr1 + 4; if ((unsigned)o < 9u) e.x += s_kb[o];
            o = tB + 1 - tr1 + 4; if ((unsigned)o < 9u) e.y += s_kb[o];
            o = tB + 2 - tr1 + 4; if ((unsigned)o < 9u) e.z += s_kb[o];
            o = tB + 3 - tr1 + 4; if ((unsigned)o < 9u) e.w += s_kb[o];
            *(float4*)(s_att + r1 * KKT_STR + tB) = e;
        }
        __syncthreads();

        // ---- out tile: 8 s-rows x 4 d per thread, 16-way t split ----
        u64 oc[8][2];
        #pragma unroll
        for (int r = 0; r < 8; r++) { oc[r][0] = pk2(0.f, 0.f); oc[r][1] = oc[r][0]; }
        #pragma unroll 2
        for (int it = 0; it < 8; it++) {
            int f4i = it * 16 + chunk;
            const float* xpb = s_xp + (size_t)f4i * 4 * XP_STR + dgrp * 4;
            ulonglong2 xv0 = *(const ulonglong2*)(xpb);
            ulonglong2 xv1 = *(const ulonglong2*)(xpb + XP_STR);
            ulonglong2 xv2 = *(const ulonglong2*)(xpb + 2 * XP_STR);
            ulonglong2 xv3 = *(const ulonglong2*)(xpb + 3 * XP_STR);
            #pragma unroll
            for (int r = 0; r < 8; r++) {
                float4 av = *(const float4*)(s_att + (sblk * 8 + r) * KKT_STR + f4i * 4);
                u64 d0 = pk2(av.x, av.x), d1 = pk2(av.y, av.y);
                u64 d2 = pk2(av.z, av.z), d3 = pk2(av.w, av.w);
                oc[r][0] = f2(d0, xv0.x, oc[r][0]); oc[r][1] = f2(d0, xv0.y, oc[r][1]);
                oc[r][0] = f2(d1, xv1.x, oc[r][0]); oc[r][1] = f2(d1, xv1.y, oc[r][1]);
                oc[r][0] = f2(d2, xv2.x, oc[r][0]); oc[r][1] = f2(d2, xv2.y, oc[r][1]);
                oc[r][0] = f2(d3, xv3.x, oc[r][0]); oc[r][1] = f2(d3, xv3.y, oc[r][1]);
            }
        }
        __syncthreads();                              // att reads done

        // ---- 3-stage partial reduction (cc-major layout) ----
        if (chunk >= 8) {
            int cc = chunk - 8;
            #pragma unroll
            for (int r = 0; r < 8; r++) {
                int o4 = (sblk * 8 + r) * 16 + dgrp;
                ulonglong2 st; st.x = oc[r][0]; st.y = oc[r][1];
                *(ulonglong2*)(s_p4 + (cc * 256 + o4) * 4) = st;
            }
        }
        __syncthreads();
        if (chunk < 8) {
            #pragma unroll
            for (int r = 0; r < 8; r++) {
                int o4 = (sblk * 8 + r) * 16 + dgrp;
                ulonglong2 pv = *(const ulonglong2*)(s_p4 + (chunk * 256 + o4) * 4);
                oc[r][0] = ad2(oc[r][0], pv.x);
                oc[r][1] = ad2(oc[r][1], pv.y);
                ulonglong2 st; st.x = oc[r][0]; st.y = oc[r][1];
                *(ulonglong2*)(s_p4 + (chunk * 256 + o4) * 4) = st;
            }
        }
        __syncthreads();
        if (tid < 256) {
            const float* pb = s_p4 + tid * 4;
            u64 s0u = pk2(0.f, 0.f), s1u = s0u;
            #pragma unroll
            for (int cc = 0; cc < 8; cc++) {
                ulonglong2 pv = *(const ulonglong2*)(pb + cc * 1024);
                s0u = ad2(s0u, pv.x); s1u = ad2(s1u, pv.y);
            }
            float2 f01 = up2(s0u), f23 = up2(s1u);
            int row = tid >> 4, dq = tid & 15;
            int sidx = s0 + row;
            size_t ob = (((size_t)n * CC + dq * 4) * SS + sidx) * VV + v;
            const size_t dst = (size_t)SS * VV;
            out[ob] = f01.x; out[ob + dst] = f01.y;
            out[ob + 2 * dst] = f23.x; out[ob + 3 * dst] = f23.y;
        }
        __syncthreads();
    }
}

extern "C" void kernel_launch(void* const* d_in, const int* in_sizes, int n_in,
                              void* d_out, int out_size)
{
    const float* x     = (const float*)d_in[0];
    const float* W     = (const float*)d_in[1];
    const float* alpha = (const float*)d_in[2];
    const float* phi   = (const float*)d_in[3];
    const float* karr  = (const float*)d_in[4];
    float* out = (float*)d_out;

    const int smemB = SMEM_FLOATS * sizeof(float);   // 222272 bytes
    cudaFuncSetAttribute(tgat3_kernel,
                         cudaFuncAttributeMaxDynamicSharedMemorySize, smemB);
    tgat3_kernel<<<NVB, 512, smemB>>>(x, W, alpha, phi, karr, out);
}